// round 1
// baseline (speedup 1.0000x reference)
#include <cuda_runtime.h>

// AdaptiveStdPooling2d: x [B=16, C=128, H=512, W=128] fp32
// kh = 64 (variance over height within bin), kw = 8 (sum of stds over width)
// out [B, C, 8, 16] fp32
//
// One warp handles one (b,c,ho) slab: 64 rows x 128 cols, contiguous 32KB.
// Lane l loads float4 -> columns 4l..4l+3. Warp covers the full 128-col row
// per iteration (perfectly coalesced 512B). kw=8 groups = 2 adjacent lanes,
// reduced with a single shfl_xor.

#define EPS 1e-14f

__global__ __launch_bounds__(128)
void adaptive_std_pool_kernel(const float* __restrict__ x,
                              float* __restrict__ out) {
    const int warp_global = blockIdx.x * 4 + (threadIdx.x >> 5); // (b*C+c)*8+ho
    const int lane = threadIdx.x & 31;

    // Slab base: warp_global * 64 rows * 128 cols floats = warp_global * 2048 float4
    const float4* __restrict__ src =
        reinterpret_cast<const float4*>(x) + (size_t)warp_global * 2048 + lane;

    float s0 = 0.f, s1 = 0.f, s2 = 0.f, s3 = 0.f;
    float q0 = 0.f, q1 = 0.f, q2 = 0.f, q3 = 0.f;

#pragma unroll 8
    for (int r = 0; r < 64; ++r) {
        float4 v = src[(size_t)r * 32];  // 32 float4 per row
        s0 += v.x; q0 = fmaf(v.x, v.x, q0);
        s1 += v.y; q1 = fmaf(v.y, v.y, q1);
        s2 += v.z; q2 = fmaf(v.z, v.z, q2);
        s3 += v.w; q3 = fmaf(v.w, v.w, q3);
    }

    const float inv = 1.0f / 64.0f;
    float m0 = s0 * inv, m1 = s1 * inv, m2 = s2 * inv, m3 = s3 * inv;
    float v0 = fmaf(-m0, m0, q0 * inv);
    float v1 = fmaf(-m1, m1, q1 * inv);
    float v2 = fmaf(-m2, m2, q2 * inv);
    float v3 = fmaf(-m3, m3, q3 * inv);

    float ssum = sqrtf(v0 + EPS) + sqrtf(v1 + EPS) +
                 sqrtf(v2 + EPS) + sqrtf(v3 + EPS);

    // kw = 8 columns = 2 lanes (4 cols each): pairwise reduce
    ssum += __shfl_xor_sync(0xffffffffu, ssum, 1);

    if ((lane & 1) == 0) {
        // wo = lane/2 in [0,16)
        out[(size_t)warp_global * 16 + (lane >> 1)] = ssum;
    }
}

extern "C" void kernel_launch(void* const* d_in, const int* in_sizes, int n_in,
                              void* d_out, int out_size) {
    const float* x = (const float*)d_in[0];
    float* out = (float*)d_out;
    // B*C*H_OUT = 16*128*8 = 16384 warps -> 4096 blocks of 128 threads
    adaptive_std_pool_kernel<<<4096, 128>>>(x, out);
}

// round 2
// speedup vs baseline: 1.0260x; 1.0260x over previous
#include <cuda_runtime.h>

// AdaptiveStdPooling2d: x [B=16, C=128, H=512, W=128] fp32
// kh = 64 (variance over height within bin), kw = 8 (sum of stds over width)
// out [B, C, 8, 16] fp32
//
// One warp per (b,c,ho) slab: 64 rows x 128 cols = 32KB contiguous.
// Lane l loads float4 -> columns 4l..4l+3; warp covers a full 512B row per
// load (perfectly coalesced). kw=8 = 2 lanes -> one shfl_xor.
//
// R2 change: streaming loads (__ldcs, evict-first) — 512MB single-pass
// stream has zero reuse; default allocate-in-L2 policy thrashes the 126MB
// L2 and costs HBM scheduling efficiency.

#define EPS 1e-14f

__global__ __launch_bounds__(128)
void adaptive_std_pool_kernel(const float* __restrict__ x,
                              float* __restrict__ out) {
    const int warp_global = blockIdx.x * 4 + (threadIdx.x >> 5); // (b*C+c)*8+ho
    const int lane = threadIdx.x & 31;

    // Slab base: warp_global * 64 rows * 32 float4/row
    const float4* __restrict__ src =
        reinterpret_cast<const float4*>(x) + (size_t)warp_global * 2048 + lane;

    float s0 = 0.f, s1 = 0.f, s2 = 0.f, s3 = 0.f;
    float q0 = 0.f, q1 = 0.f, q2 = 0.f, q3 = 0.f;

#pragma unroll 16
    for (int r = 0; r < 64; ++r) {
        float4 v = __ldcs(src + (size_t)r * 32);  // streaming: evict-first
        s0 += v.x; q0 = fmaf(v.x, v.x, q0);
        s1 += v.y; q1 = fmaf(v.y, v.y, q1);
        s2 += v.z; q2 = fmaf(v.z, v.z, q2);
        s3 += v.w; q3 = fmaf(v.w, v.w, q3);
    }

    const float inv = 1.0f / 64.0f;
    float m0 = s0 * inv, m1 = s1 * inv, m2 = s2 * inv, m3 = s3 * inv;
    float v0 = fmaf(-m0, m0, q0 * inv);
    float v1 = fmaf(-m1, m1, q1 * inv);
    float v2 = fmaf(-m2, m2, q2 * inv);
    float v3 = fmaf(-m3, m3, q3 * inv);

    float ssum = sqrtf(v0 + EPS) + sqrtf(v1 + EPS) +
                 sqrtf(v2 + EPS) + sqrtf(v3 + EPS);

    // kw = 8 columns = 2 lanes (4 cols each): pairwise reduce
    ssum += __shfl_xor_sync(0xffffffffu, ssum, 1);

    if ((lane & 1) == 0) {
        out[(size_t)warp_global * 16 + (lane >> 1)] = ssum;
    }
}

extern "C" void kernel_launch(void* const* d_in, const int* in_sizes, int n_in,
                              void* d_out, int out_size) {
    const float* x = (const float*)d_in[0];
    float* out = (float*)d_out;
    adaptive_std_pool_kernel<<<4096, 128>>>(x, out);
}